// round 14
// baseline (speedup 1.0000x reference)
#include <cuda_runtime.h>
#include <math.h>

#define DD   128        // embedding dim
#define HH   256        // hyper hidden
#define EMAX 500000
#define SLOTMAX 250000
#define CAP  8          // max edges tracked per group (P(c>8) ~ 1e-12/pair)
#define SSTR (DD + 4)   // padded S row stride

// ---------------- device scratch (static; no allocation) ----------------
__device__ float g_h2 [HH];                    // hypernet hidden layer 2
__device__ float g_M [DD*DD];
__device__ int   g_counts[EMAX];
__device__ int   g_slotg [SLOTMAX];            // slot -> group id
__device__ int   g_geidx [(size_t)EMAX * CAP]; // per-group edge lists (32B rows)
__device__ int   g_nslots;
__device__ int   g_tile;                       // dynamic tile counter

// ---------------- helpers ----------------
__device__ __forceinline__ unsigned long long pack2(float s) {
    unsigned long long r;
    asm("mov.b64 %0, {%1, %1};" : "=l"(r) : "r"(__float_as_uint(s)));
    return r;
}
__device__ __forceinline__ void fma2(unsigned long long& d,
                                     unsigned long long a, unsigned long long b) {
    asm("fma.rn.f32x2 %0, %1, %2, %0;" : "+l"(d) : "l"(a), "l"(b));
}

// ---------------- kernel 1: zero + out=1 + DISTRIBUTED fc1/fc2 ----------
__global__ void k_zero_hyper(int E, float* __restrict__ out,
                             const float* __restrict__ pref,
                             const float* __restrict__ fc1_w, const float* __restrict__ fc1_b,
                             const float* __restrict__ fc2_w, const float* __restrict__ fc2_b) {
    int i = blockIdx.x * blockDim.x + threadIdx.x;   // quad index (E % 4 == 0)
    if (i * 4 < E) {
        ((int4*)g_counts)[i] = make_int4(0, 0, 0, 0);
        ((float4*)out)[i]    = make_float4(1.f, 1.f, 1.f, 1.f);  // singleton answer
    }
    if (i == 0) { g_nslots = 0; g_tile = 0; }

    int b = blockIdx.x;
    if (b < HH) {                     // block b computes h2[b]
        __shared__ float red[8];
        int t = threadIdx.x;
        int lane = t & 31, w = t >> 5;
        float p0 = pref[0], p1 = pref[1];
        float h1t = p0 * __ldg(&fc1_w[2*t]) + p1 * __ldg(&fc1_w[2*t + 1])
                  + __ldg(&fc1_b[t]);
        float p = h1t * __ldg(&fc2_w[b*HH + t]);
        #pragma unroll
        for (int off = 16; off > 0; off >>= 1)
            p += __shfl_xor_sync(0xffffffffu, p, off);
        if (lane == 0) red[w] = p;
        __syncthreads();
        if (t == 0) {
            float a = __ldg(&fc2_b[b]);
            #pragma unroll
            for (int ww = 0; ww < 8; ww++) a += red[ww];
            g_h2[b] = a;
        }
    }
}

// ---------------- kernel 2: count + lists + BLOCK-AGGREGATED slot claim --
__global__ void k_count_m(const int* __restrict__ seg, int E,
                          const float* __restrict__ fc3_w, const float* __restrict__ fc3_b,
                          const float* __restrict__ wq_w, const float* __restrict__ wk_w) {
    __shared__ int s_cnt, s_base;
    __shared__ int s_list[2048];
    int t = threadIdx.x;
    int lane = t & 31;
    if (t == 0) s_cnt = 0;
    __syncthreads();

    int base = (blockIdx.x * blockDim.x + t) * 8;
    bool valid = base < E;                    // E % 8 == 0
    int gs[8];
    int old[8];
    #pragma unroll
    for (int j = 0; j < 8; j++) { gs[j] = 0; old[j] = -1; }
    if (valid) {
        int4 a = *(const int4*)&seg[base];
        int4 b = *(const int4*)&seg[base + 4];
        gs[0]=a.x; gs[1]=a.y; gs[2]=a.z; gs[3]=a.w;
        gs[4]=b.x; gs[5]=b.y; gs[6]=b.z; gs[7]=b.w;
        #pragma unroll
        for (int j = 0; j < 8; j++) old[j] = atomicAdd(&g_counts[gs[j]], 1);
        #pragma unroll
        for (int j = 0; j < 8; j++)
            if (old[j] < CAP) g_geidx[(size_t)gs[j] * CAP + old[j]] = base + j;
        #pragma unroll
        for (int j = 0; j < 8; j++)
            if (old[j] == 1) s_list[atomicAdd(&s_cnt, 1)] = gs[j];
    }
    __syncthreads();
    if (t == 0) s_base = atomicAdd(&g_nslots, s_cnt);
    __syncthreads();
    for (int i = t; i < s_cnt; i += blockDim.x)
        g_slotg[s_base + i] = s_list[i];

    // ---- fc3 (redundant per block) + M rows (blocks 0..63) ----
    if (blockIdx.x < DD / 2) {
        __shared__ float red[4][8];
        __shared__ float mid[4];
        __shared__ float col[2][DD];
        int w = t >> 5;
        float hv = __ldg(&g_h2[t]);
        #pragma unroll
        for (int o = 0; o < 4; o++) {
            float p = hv * __ldg(&fc3_w[o*HH + t]);
            #pragma unroll
            for (int off = 16; off > 0; off >>= 1)
                p += __shfl_xor_sync(0xffffffffu, p, off);
            if (lane == 0) red[o][w] = p;
        }
        __syncthreads();
        if (t < 4) {
            float a = __ldg(&fc3_b[t]);
            #pragma unroll
            for (int ww = 0; ww < 8; ww++) a += red[t][ww];
            mid[t] = a;
        }
        __syncthreads();
        float m0 = mid[0], m1 = mid[1], m2 = mid[2], m3 = mid[3];

        int half = t >> 7;
        int c = t & (DD - 1);
        int r = blockIdx.x * 2 + half;
        const float2* wq2 = (const float2*)wq_w;
        const float2* wk2 = (const float2*)wk_w;
        float2 q = __ldg(&wq2[c*DD + r]);    // Wq[c, r]
        col[half][c] = m0 * q.x + m1 * q.y;
        __syncthreads();
        float acc = 0.f;
        #pragma unroll 16
        for (int o = 0; o < DD; o++) {
            float2 kv = __ldg(&wk2[o*DD + c]);
            acc += col[half][o] * (m2 * kv.x + m3 * kv.y);
        }
        g_M[r*DD + c] = acc;
    }
}

// ---------------- kernel 3: gather + GEMM + score + softmax ------------
// Pipelined meta prefetch; e0..e3 come from ONE int4 (CAP=8, 32B rows).
__global__ void __launch_bounds__(512, 2) k_u_score(
        const float* __restrict__ emb, const float* __restrict__ dists,
        const float* __restrict__ pref, float* __restrict__ out) {
    extern __shared__ float sh[];
    float* Msh  = sh;                          // DD*DD
    float* S    = sh + DD*DD;                  // 64 rows, stride SSTR
    int*  metaI = (int*)(S + 64*SSTR);         // 2 bufs x [sg|sc|e0|e1|e2|e3] x 64
    float* metaF = (float*)(metaI + 2*384);    // 2 bufs x [de0|de1] x 64
    __shared__ int curTile;
    int t = threadIdx.x;
    int lane = t & 31, w = t >> 5;             // w: 0..15
    for (int i = t; i < DD*DD/4; i += 512)
        ((float4*)Msh)[i] = ((const float4*)g_M)[i];
    float p0 = pref[0], p1 = pref[1];
    const float inv_scale = 0.011048543456039805f;  // 1/(8*sqrt(128))
    const float inv_sqrt2 = 0.7071067811865476f;
    int tx = t & 15, typ = t >> 4;
    int c0 = tx * 8;
    int ns = g_nslots;
    int ntiles = (ns + 63) >> 6;

    // lanes 0..3 each fetch one slot's chain: slotg -> {counts, e-list int4}
    auto prefetch = [&](int tile, int buf) {
        if (lane < 4) {
            int s0 = tile * 64;
            int nk = min(64, ns - s0);
            int k  = w * 4 + lane;
            int sg = (k < nk) ? __ldg(&g_slotg[s0 + k]) : -1;
            int sc = 0;
            int4 ev = make_int4(0, 0, 0, 0);
            float de0 = 0.f, de1 = 0.f;
            if (sg >= 0) {
                sc = __ldg(&g_counts[sg]);
                ev = __ldg((const int4*)&g_geidx[(size_t)sg * CAP]);  // e0..e3
                float2 a = __ldg((const float2*)&dists[2*ev.x]);
                float2 b = __ldg((const float2*)&dists[2*ev.y]);
                de0 = p0 * a.x + p1 * a.y;
                de1 = p0 * b.x + p1 * b.y;
            }
            int*   MI = metaI + buf * 384;
            float* MF = metaF + buf * 128;
            MI[k] = sg; MI[64 + k] = sc;
            MI[128 + k] = ev.x; MI[192 + k] = ev.y;
            MI[256 + k] = ev.z; MI[320 + k] = ev.w;
            MF[k] = de0; MF[64 + k] = de1;
        }
    };

    if (t == 0) curTile = atomicAdd(&g_tile, 1);
    __syncthreads();
    int ct = curTile;
    int buf = 0;
    if (ct < ntiles) prefetch(ct, 0);

    while (ct < ntiles) {
        if (t == 0) curTile = atomicAdd(&g_tile, 1);
        int*   MI = metaI + buf * 384;
        float* MF = metaF + buf * 128;

        // ---- Phase A: gather + sum (x0..x3 unconditional: indices always
        //      in-range; e2/e3 masked into the sum; MLP = 16 per lane) ----
        #pragma unroll
        for (int ss = 0; ss < 4; ss++) {
            int k  = w * 4 + ss;
            int sg = MI[k];
            float4 a = make_float4(0.f, 0.f, 0.f, 0.f);
            if (sg >= 0) {
                int cc = min(MI[64 + k], CAP);
                float4 x0 = __ldg(&((const float4*)(emb + (size_t)MI[128+k] * DD))[lane]);
                float4 x1 = __ldg(&((const float4*)(emb + (size_t)MI[192+k] * DD))[lane]);
                float4 x2 = __ldg(&((const float4*)(emb + (size_t)MI[256+k] * DD))[lane]);
                float4 x3 = __ldg(&((const float4*)(emb + (size_t)MI[320+k] * DD))[lane]);
                float m2 = (cc > 2) ? 1.f : 0.f;
                float m3 = (cc > 3) ? 1.f : 0.f;
                a.x = x0.x + x1.x + m2*x2.x + m3*x3.x;
                a.y = x0.y + x1.y + m2*x2.y + m3*x3.y;
                a.z = x0.z + x1.z + m2*x2.z + m3*x3.z;
                a.w = x0.w + x1.w + m2*x2.w + m3*x3.w;
                for (int j = 4; j < cc; j++) {
                    int e = __ldg(&g_geidx[(size_t)sg * CAP + j]);
                    float4 x = __ldg(&((const float4*)(emb + (size_t)e * DD))[lane]);
                    a.x += x.x; a.y += x.y; a.z += x.z; a.w += x.w;
                }
            }
            *(float4*)&S[k * SSTR + lane * 4] = a;
        }
        __syncthreads();                  // S ready; curTile visible

        int nt = curTile;
        if (nt < ntiles) prefetch(nt, buf ^ 1);   // hidden under GEMM

        // ---- Phase B: u[k][c] = sum_d S[k][d] * M[d][c] ----
        unsigned long long acc[2][4];
        #pragma unroll
        for (int i = 0; i < 2; i++)
            #pragma unroll
            for (int j = 0; j < 4; j++) acc[i][j] = 0ull;
        #pragma unroll 4
        for (int d = 0; d < DD; d++) {
            const double2* mp = (const double2*)&Msh[d*DD + c0];
            double2 ma = mp[0];
            double2 mb = mp[1];
            unsigned long long m0 = __double_as_longlong(ma.x);
            unsigned long long m1 = __double_as_longlong(ma.y);
            unsigned long long m2 = __double_as_longlong(mb.x);
            unsigned long long m3 = __double_as_longlong(mb.y);
            unsigned long long sa = pack2(S[(2*typ    ) * SSTR + d]);
            unsigned long long sb = pack2(S[(2*typ + 1) * SSTR + d]);
            fma2(acc[0][0], m0, sa); fma2(acc[0][1], m1, sa);
            fma2(acc[0][2], m2, sa); fma2(acc[0][3], m3, sa);
            fma2(acc[1][0], m0, sb); fma2(acc[1][1], m1, sb);
            fma2(acc[1][2], m2, sb); fma2(acc[1][3], m3, sb);
        }
        __syncthreads();
        #pragma unroll
        for (int i = 0; i < 2; i++) {
            double2* row = (double2*)&S[(2*typ + i) * SSTR + c0];
            row[0] = make_double2(__longlong_as_double(acc[i][0]),
                                  __longlong_as_double(acc[i][1]));
            row[1] = make_double2(__longlong_as_double(acc[i][2]),
                                  __longlong_as_double(acc[i][3]));
        }
        __syncthreads();

        // ---- Phase C: per-slot softmax (meta from smem; emb L2-hot) ----
        #pragma unroll
        for (int ss = 0; ss < 4; ss++) {
            int k  = w * 4 + ss;
            int sg = MI[k];
            if (sg < 0) continue;
            int sc = MI[64 + k];
            float fc = (float)sc;
            int cc = min(sc, CAP);
            float4 u4 = *(float4*)&S[k * SSTR + lane * 4];
            float denom = 0.f, myex = 0.f;
            int mye = 0;
            for (int j = 0; j < cc; j++) {
                int e; float de;
                if (j == 0)      { e = MI[128 + k]; de = MF[k]; }
                else if (j == 1) { e = MI[192 + k]; de = MF[64 + k]; }
                else {
                    e = (j == 2) ? MI[256 + k] : (j == 3) ? MI[320 + k]
                        : __ldg(&g_geidx[(size_t)sg * CAP + j]);
                    float2 dd = __ldg((const float2*)&dists[2*e]);
                    de = p0 * dd.x + p1 * dd.y;
                }
                float4 x = __ldg(&((const float4*)(emb + (size_t)e * DD))[lane]);
                float dot = u4.x*x.x + u4.y*x.y + u4.z*x.z + u4.w*x.w;
                #pragma unroll
                for (int o = 16; o > 0; o >>= 1)
                    dot += __shfl_xor_sync(0xffffffffu, dot, o);
                float s = dot * inv_scale / fc - de * inv_sqrt2;
                float ex = expf(10.0f * tanhf(s));   // clipped: exp is fp32-safe
                denom += ex;
                if (lane == j) { mye = e; myex = ex; }
            }
            if (lane < cc) out[mye] = myex / denom;
        }
        __syncthreads();
        buf ^= 1;
        ct = nt;
    }
}

// no-op: shifts ncu's fixed capture slot onto a different kernel next round
__global__ void k_nop() {}

// ---------------- launch ----------------
extern "C" void kernel_launch(void* const* d_in, const int* in_sizes, int n_in,
                              void* d_out, int out_size) {
    const float* pref     = (const float*)d_in[0];
    const float* dists    = (const float*)d_in[1];
    const float* edge_emb = (const float*)d_in[2];
    const int*   seg      = (const int*)  d_in[3];
    const float* fc1_w    = (const float*)d_in[4];
    const float* fc1_b    = (const float*)d_in[5];
    const float* fc2_w    = (const float*)d_in[6];
    const float* fc2_b    = (const float*)d_in[7];
    const float* fc3_w    = (const float*)d_in[8];
    const float* fc3_b    = (const float*)d_in[9];
    const float* wq_w     = (const float*)d_in[10];
    const float* wk_w     = (const float*)d_in[11];
    float* out = (float*)d_out;

    int E   = in_sizes[3];
    int EB4 = (E/4 + 255) / 256;
    int EB8 = (E/8 + 255) / 256;

    const int KU_SMEM = (DD*DD + 64*SSTR) * (int)sizeof(float)
                      + 2*384*(int)sizeof(int) + 2*128*(int)sizeof(float);
    cudaFuncSetAttribute(k_u_score, cudaFuncAttributeMaxDynamicSharedMemorySize, KU_SMEM);

    k_zero_hyper <<<EB4, 256>>>(E, out, pref, fc1_w, fc1_b, fc2_w, fc2_b);
    k_count_m    <<<EB8, 256>>>(seg, E, fc3_w, fc3_b, wq_w, wk_w);
    k_u_score    <<<296, 512, KU_SMEM>>>(edge_emb, dists, pref, out);
    k_nop        <<<1, 32>>>();
}

// round 15
// speedup vs baseline: 1.0229x; 1.0229x over previous
#include <cuda_runtime.h>
#include <math.h>

#define DD   128        // embedding dim
#define HH   256        // hyper hidden
#define EMAX 500000
#define SLOTMAX 250000
#define CAP  8          // max edges tracked per group (P(c>8) ~ 1e-12/pair)
#define SSTR (DD + 4)   // padded S row stride

// ---------------- device scratch (static; no allocation) ----------------
__device__ float g_h2 [HH];                    // hypernet hidden layer 2
__device__ float g_M [DD*DD];
__device__ int   g_counts[EMAX];
__device__ int   g_slotg [SLOTMAX];            // slot -> group id
__device__ int   g_geidx [(size_t)EMAX * CAP]; // per-group edge lists (32B rows)
__device__ int   g_nslots;
__device__ int   g_tile;                       // dynamic tile counter

// ---------------- helpers ----------------
__device__ __forceinline__ unsigned long long pack2(float s) {
    unsigned long long r;
    asm("mov.b64 %0, {%1, %1};" : "=l"(r) : "r"(__float_as_uint(s)));
    return r;
}
__device__ __forceinline__ void fma2(unsigned long long& d,
                                     unsigned long long a, unsigned long long b) {
    asm("fma.rn.f32x2 %0, %1, %2, %0;" : "+l"(d) : "l"(a), "l"(b));
}

// no-op FIRST: shifts ncu's fixed capture slot (launch #4) onto k_u_score
__global__ void k_nop() {}

// ---------------- kernel 1: zero + out=1 + DISTRIBUTED fc1/fc2 ----------
__global__ void k_zero_hyper(int E, float* __restrict__ out,
                             const float* __restrict__ pref,
                             const float* __restrict__ fc1_w, const float* __restrict__ fc1_b,
                             const float* __restrict__ fc2_w, const float* __restrict__ fc2_b) {
    int i = blockIdx.x * blockDim.x + threadIdx.x;   // quad index (E % 4 == 0)
    if (i * 4 < E) {
        ((int4*)g_counts)[i] = make_int4(0, 0, 0, 0);
        ((float4*)out)[i]    = make_float4(1.f, 1.f, 1.f, 1.f);  // singleton answer
    }
    if (i == 0) { g_nslots = 0; g_tile = 0; }

    int b = blockIdx.x;
    if (b < HH) {                     // block b computes h2[b]
        __shared__ float red[8];
        int t = threadIdx.x;
        int lane = t & 31, w = t >> 5;
        float p0 = pref[0], p1 = pref[1];
        float h1t = p0 * __ldg(&fc1_w[2*t]) + p1 * __ldg(&fc1_w[2*t + 1])
                  + __ldg(&fc1_b[t]);
        float p = h1t * __ldg(&fc2_w[b*HH + t]);
        #pragma unroll
        for (int off = 16; off > 0; off >>= 1)
            p += __shfl_xor_sync(0xffffffffu, p, off);
        if (lane == 0) red[w] = p;
        __syncthreads();
        if (t == 0) {
            float a = __ldg(&fc2_b[b]);
            #pragma unroll
            for (int ww = 0; ww < 8; ww++) a += red[ww];
            g_h2[b] = a;
        }
    }
}

// ---------------- kernel 2: count + lists + BLOCK-AGGREGATED slot claim --
__global__ void k_count_m(const int* __restrict__ seg, int E,
                          const float* __restrict__ fc3_w, const float* __restrict__ fc3_b,
                          const float* __restrict__ wq_w, const float* __restrict__ wk_w) {
    __shared__ int s_cnt, s_base;
    __shared__ int s_list[2048];
    int t = threadIdx.x;
    int lane = t & 31;
    if (t == 0) s_cnt = 0;
    __syncthreads();

    int base = (blockIdx.x * blockDim.x + t) * 8;
    bool valid = base < E;                    // E % 8 == 0
    int gs[8];
    int old[8];
    #pragma unroll
    for (int j = 0; j < 8; j++) { gs[j] = 0; old[j] = -1; }
    if (valid) {
        int4 a = *(const int4*)&seg[base];
        int4 b = *(const int4*)&seg[base + 4];
        gs[0]=a.x; gs[1]=a.y; gs[2]=a.z; gs[3]=a.w;
        gs[4]=b.x; gs[5]=b.y; gs[6]=b.z; gs[7]=b.w;
        #pragma unroll
        for (int j = 0; j < 8; j++) old[j] = atomicAdd(&g_counts[gs[j]], 1);
        #pragma unroll
        for (int j = 0; j < 8; j++)
            if (old[j] < CAP) g_geidx[(size_t)gs[j] * CAP + old[j]] = base + j;
        #pragma unroll
        for (int j = 0; j < 8; j++)
            if (old[j] == 1) s_list[atomicAdd(&s_cnt, 1)] = gs[j];
    }
    __syncthreads();
    if (t == 0) s_base = atomicAdd(&g_nslots, s_cnt);
    __syncthreads();
    for (int i = t; i < s_cnt; i += blockDim.x)
        g_slotg[s_base + i] = s_list[i];

    // ---- fc3 (redundant per block) + M rows (blocks 0..63) ----
    if (blockIdx.x < DD / 2) {
        __shared__ float red[4][8];
        __shared__ float mid[4];
        __shared__ float col[2][DD];
        int w = t >> 5;
        float hv = __ldg(&g_h2[t]);
        #pragma unroll
        for (int o = 0; o < 4; o++) {
            float p = hv * __ldg(&fc3_w[o*HH + t]);
            #pragma unroll
            for (int off = 16; off > 0; off >>= 1)
                p += __shfl_xor_sync(0xffffffffu, p, off);
            if (lane == 0) red[o][w] = p;
        }
        __syncthreads();
        if (t < 4) {
            float a = __ldg(&fc3_b[t]);
            #pragma unroll
            for (int ww = 0; ww < 8; ww++) a += red[t][ww];
            mid[t] = a;
        }
        __syncthreads();
        float m0 = mid[0], m1 = mid[1], m2 = mid[2], m3 = mid[3];

        int half = t >> 7;
        int c = t & (DD - 1);
        int r = blockIdx.x * 2 + half;
        const float2* wq2 = (const float2*)wq_w;
        const float2* wk2 = (const float2*)wk_w;
        float2 q = __ldg(&wq2[c*DD + r]);    // Wq[c, r]
        col[half][c] = m0 * q.x + m1 * q.y;
        __syncthreads();
        float acc = 0.f;
        #pragma unroll 16
        for (int o = 0; o < DD; o++) {
            float2 kv = __ldg(&wk2[o*DD + c]);
            acc += col[half][o] * (m2 * kv.x + m3 * kv.y);
        }
        g_M[r*DD + c] = acc;
    }
}

// ---------------- kernel 3: gather + GEMM + score + softmax ------------
// Pipelined meta prefetch; e0..e3 in one int4; de0..de3 precomputed.
__global__ void __launch_bounds__(512, 2) k_u_score(
        const float* __restrict__ emb, const float* __restrict__ dists,
        const float* __restrict__ pref, float* __restrict__ out) {
    extern __shared__ float sh[];
    float* Msh  = sh;                          // DD*DD
    float* S    = sh + DD*DD;                  // 64 rows, stride SSTR
    int*  metaI = (int*)(S + 64*SSTR);         // 2 bufs x [sg|sc|e0..e3] x 64
    float* metaF = (float*)(metaI + 2*384);    // 2 bufs x [de0..de3] x 64
    __shared__ int curTile;
    int t = threadIdx.x;
    int lane = t & 31, w = t >> 5;             // w: 0..15
    for (int i = t; i < DD*DD/4; i += 512)
        ((float4*)Msh)[i] = ((const float4*)g_M)[i];
    float p0 = pref[0], p1 = pref[1];
    const float inv_scale = 0.011048543456039805f;  // 1/(8*sqrt(128))
    const float inv_sqrt2 = 0.7071067811865476f;
    int tx = t & 15, typ = t >> 4;
    int c0 = tx * 8;
    int ns = g_nslots;
    int ntiles = (ns + 63) >> 6;

    // lanes 0..3 each fetch one slot's chain: slotg -> {counts, e-list int4,
    // dists for e0..e3} (stale e2/e3 indices are in-range => loads safe)
    auto prefetch = [&](int tile, int buf) {
        if (lane < 4) {
            int s0 = tile * 64;
            int nk = min(64, ns - s0);
            int k  = w * 4 + lane;
            int sg = (k < nk) ? __ldg(&g_slotg[s0 + k]) : -1;
            int sc = 0;
            int4 ev = make_int4(0, 0, 0, 0);
            float de0 = 0.f, de1 = 0.f, de2 = 0.f, de3 = 0.f;
            if (sg >= 0) {
                sc = __ldg(&g_counts[sg]);
                ev = __ldg((const int4*)&g_geidx[(size_t)sg * CAP]);  // e0..e3
                float2 a = __ldg((const float2*)&dists[2*ev.x]);
                float2 b = __ldg((const float2*)&dists[2*ev.y]);
                float2 c = __ldg((const float2*)&dists[2*ev.z]);
                float2 d = __ldg((const float2*)&dists[2*ev.w]);
                de0 = p0 * a.x + p1 * a.y;
                de1 = p0 * b.x + p1 * b.y;
                de2 = p0 * c.x + p1 * c.y;
                de3 = p0 * d.x + p1 * d.y;
            }
            int*   MI = metaI + buf * 384;
            float* MF = metaF + buf * 256;
            MI[k] = sg; MI[64 + k] = sc;
            MI[128 + k] = ev.x; MI[192 + k] = ev.y;
            MI[256 + k] = ev.z; MI[320 + k] = ev.w;
            MF[k] = de0; MF[64 + k] = de1; MF[128 + k] = de2; MF[192 + k] = de3;
        }
    };

    if (t == 0) curTile = atomicAdd(&g_tile, 1);
    __syncthreads();
    int ct = curTile;
    int buf = 0;
    if (ct < ntiles) prefetch(ct, 0);

    while (ct < ntiles) {
        if (t == 0) curTile = atomicAdd(&g_tile, 1);
        int*   MI = metaI + buf * 384;
        float* MF = metaF + buf * 256;

        // ---- Phase A: gather + sum (unconditional x0..x3, MLP = 16/lane) ----
        #pragma unroll
        for (int ss = 0; ss < 4; ss++) {
            int k  = w * 4 + ss;
            int sg = MI[k];
            float4 a = make_float4(0.f, 0.f, 0.f, 0.f);
            if (sg >= 0) {
                int cc = min(MI[64 + k], CAP);
                float4 x0 = __ldg(&((const float4*)(emb + (size_t)MI[128+k] * DD))[lane]);
                float4 x1 = __ldg(&((const float4*)(emb + (size_t)MI[192+k] * DD))[lane]);
                float4 x2 = __ldg(&((const float4*)(emb + (size_t)MI[256+k] * DD))[lane]);
                float4 x3 = __ldg(&((const float4*)(emb + (size_t)MI[320+k] * DD))[lane]);
                float m2 = (cc > 2) ? 1.f : 0.f;
                float m3 = (cc > 3) ? 1.f : 0.f;
                a.x = x0.x + x1.x + m2*x2.x + m3*x3.x;
                a.y = x0.y + x1.y + m2*x2.y + m3*x3.y;
                a.z = x0.z + x1.z + m2*x2.z + m3*x3.z;
                a.w = x0.w + x1.w + m2*x2.w + m3*x3.w;
                for (int j = 4; j < cc; j++) {
                    int e = __ldg(&g_geidx[(size_t)sg * CAP + j]);
                    float4 x = __ldg(&((const float4*)(emb + (size_t)e * DD))[lane]);
                    a.x += x.x; a.y += x.y; a.z += x.z; a.w += x.w;
                }
            }
            *(float4*)&S[k * SSTR + lane * 4] = a;
        }
        __syncthreads();                  // S ready; curTile visible

        int nt = curTile;
        if (nt < ntiles) prefetch(nt, buf ^ 1);   // hidden under GEMM

        // ---- Phase B: u[k][c] = sum_d S[k][d] * M[d][c] ----
        unsigned long long acc[2][4];
        #pragma unroll
        for (int i = 0; i < 2; i++)
            #pragma unroll
            for (int j = 0; j < 4; j++) acc[i][j] = 0ull;
        #pragma unroll 4
        for (int d = 0; d < DD; d++) {
            const double2* mp = (const double2*)&Msh[d*DD + c0];
            double2 ma = mp[0];
            double2 mb = mp[1];
            unsigned long long m0 = __double_as_longlong(ma.x);
            unsigned long long m1 = __double_as_longlong(ma.y);
            unsigned long long m2 = __double_as_longlong(mb.x);
            unsigned long long m3 = __double_as_longlong(mb.y);
            unsigned long long sa = pack2(S[(2*typ    ) * SSTR + d]);
            unsigned long long sb = pack2(S[(2*typ + 1) * SSTR + d]);
            fma2(acc[0][0], m0, sa); fma2(acc[0][1], m1, sa);
            fma2(acc[0][2], m2, sa); fma2(acc[0][3], m3, sa);
            fma2(acc[1][0], m0, sb); fma2(acc[1][1], m1, sb);
            fma2(acc[1][2], m2, sb); fma2(acc[1][3], m3, sb);
        }
        __syncthreads();
        #pragma unroll
        for (int i = 0; i < 2; i++) {
            double2* row = (double2*)&S[(2*typ + i) * SSTR + c0];
            row[0] = make_double2(__longlong_as_double(acc[i][0]),
                                  __longlong_as_double(acc[i][1]));
            row[1] = make_double2(__longlong_as_double(acc[i][2]),
                                  __longlong_as_double(acc[i][3]));
        }
        __syncthreads();

        // ---- Phase C: per-slot softmax (meta + dists fully cached j<4) ----
        #pragma unroll
        for (int ss = 0; ss < 4; ss++) {
            int k  = w * 4 + ss;
            int sg = MI[k];
            if (sg < 0) continue;
            int sc = MI[64 + k];
            float fc = (float)sc;
            int cc = min(sc, CAP);
            float4 u4 = *(float4*)&S[k * SSTR + lane * 4];
            float denom = 0.f, myex = 0.f;
            int mye = 0;
            for (int j = 0; j < cc; j++) {
                int e; float de;
                if (j < 4) { e = MI[128 + 64*j + k]; de = MF[64*j + k]; }
                else {
                    e = __ldg(&g_geidx[(size_t)sg * CAP + j]);
                    float2 dd = __ldg((const float2*)&dists[2*e]);
                    de = p0 * dd.x + p1 * dd.y;
                }
                float4 x = __ldg(&((const float4*)(emb + (size_t)e * DD))[lane]);
                float dot = u4.x*x.x + u4.y*x.y + u4.z*x.z + u4.w*x.w;
                #pragma unroll
                for (int o = 16; o > 0; o >>= 1)
                    dot += __shfl_xor_sync(0xffffffffu, dot, o);
                float s = dot * inv_scale / fc - de * inv_sqrt2;
                float ex = expf(10.0f * tanhf(s));   // clipped: exp is fp32-safe
                denom += ex;
                if (lane == j) { mye = e; myex = ex; }
            }
            if (lane < cc) out[mye] = myex / denom;
        }
        __syncthreads();
        buf ^= 1;
        ct = nt;
    }
}

// ---------------- launch ----------------
extern "C" void kernel_launch(void* const* d_in, const int* in_sizes, int n_in,
                              void* d_out, int out_size) {
    const float* pref     = (const float*)d_in[0];
    const float* dists    = (const float*)d_in[1];
    const float* edge_emb = (const float*)d_in[2];
    const int*   seg      = (const int*)  d_in[3];
    const float* fc1_w    = (const float*)d_in[4];
    const float* fc1_b    = (const float*)d_in[5];
    const float* fc2_w    = (const float*)d_in[6];
    const float* fc2_b    = (const float*)d_in[7];
    const float* fc3_w    = (const float*)d_in[8];
    const float* fc3_b    = (const float*)d_in[9];
    const float* wq_w     = (const float*)d_in[10];
    const float* wk_w     = (const float*)d_in[11];
    float* out = (float*)d_out;

    int E   = in_sizes[3];
    int EB4 = (E/4 + 255) / 256;
    int EB8 = (E/8 + 255) / 256;

    const int KU_SMEM = (DD*DD + 64*SSTR) * (int)sizeof(float)
                      + 2*384*(int)sizeof(int) + 2*256*(int)sizeof(float);
    cudaFuncSetAttribute(k_u_score, cudaFuncAttributeMaxDynamicSharedMemorySize, KU_SMEM);

    k_nop        <<<1, 32>>>();          // shifts ncu capture onto k_u_score
    k_zero_hyper <<<EB4, 256>>>(E, out, pref, fc1_w, fc1_b, fc2_w, fc2_b);
    k_count_m    <<<EB8, 256>>>(seg, E, fc3_w, fc3_b, wq_w, wk_w);
    k_u_score    <<<296, 512, KU_SMEM>>>(edge_emb, dists, pref, out);
}

// round 16
// speedup vs baseline: 1.3458x; 1.3157x over previous
#include <cuda_runtime.h>
#include <math.h>

#define DD   128        // embedding dim
#define HH   256        // hyper hidden
#define EMAX 500000
#define SLOTMAX 250000
#define CAP  8          // max edges tracked per group (P(c>8) ~ 1e-12/pair)
#define SSTR (DD + 4)   // padded S row stride

// ---------------- device scratch (static; no allocation) ----------------
__device__ float g_h2 [HH];                    // hypernet hidden layer 2
__device__ float g_M [DD*DD];
__device__ int   g_counts[EMAX];
__device__ int   g_slotg [SLOTMAX];            // slot -> group id
__device__ int   g_geidx [(size_t)EMAX * CAP]; // per-group edge lists (32B rows)
__device__ int   g_nslots;
__device__ int   g_tile;                       // dynamic tile counter

// ---------------- helpers ----------------
__device__ __forceinline__ unsigned long long pack2(float s) {
    unsigned long long r;
    asm("mov.b64 %0, {%1, %1};" : "=l"(r) : "r"(__float_as_uint(s)));
    return r;
}
__device__ __forceinline__ void fma2(unsigned long long& d,
                                     unsigned long long a, unsigned long long b) {
    asm("fma.rn.f32x2 %0, %1, %2, %0;" : "+l"(d) : "l"(a), "l"(b));
}

// no-op FIRST: keeps ncu's capture slot (launch #4) on k_u_score
__global__ void k_nop() {}

// ---------------- kernel 1: zero + out=1 + DISTRIBUTED fc1/fc2 ----------
__global__ void k_zero_hyper(int E, float* __restrict__ out,
                             const float* __restrict__ pref,
                             const float* __restrict__ fc1_w, const float* __restrict__ fc1_b,
                             const float* __restrict__ fc2_w, const float* __restrict__ fc2_b) {
    int i = blockIdx.x * blockDim.x + threadIdx.x;   // quad index (E % 4 == 0)
    if (i * 4 < E) {
        ((int4*)g_counts)[i] = make_int4(0, 0, 0, 0);
        ((float4*)out)[i]    = make_float4(1.f, 1.f, 1.f, 1.f);  // singleton answer
    }
    if (i == 0) { g_nslots = 0; g_tile = 0; }

    int b = blockIdx.x;
    if (b < HH) {                     // block b computes h2[b]
        __shared__ float red[8];
        int t = threadIdx.x;
        int lane = t & 31, w = t >> 5;
        float p0 = pref[0], p1 = pref[1];
        float h1t = p0 * __ldg(&fc1_w[2*t]) + p1 * __ldg(&fc1_w[2*t + 1])
                  + __ldg(&fc1_b[t]);
        float p = h1t * __ldg(&fc2_w[b*HH + t]);
        #pragma unroll
        for (int off = 16; off > 0; off >>= 1)
            p += __shfl_xor_sync(0xffffffffu, p, off);
        if (lane == 0) red[w] = p;
        __syncthreads();
        if (t == 0) {
            float a = __ldg(&fc2_b[b]);
            #pragma unroll
            for (int ww = 0; ww < 8; ww++) a += red[ww];
            g_h2[b] = a;
        }
    }
}

// ---------------- kernel 2: count + lists + BLOCK-AGGREGATED slot claim --
__global__ void k_count_m(const int* __restrict__ seg, int E,
                          const float* __restrict__ fc3_w, const float* __restrict__ fc3_b,
                          const float* __restrict__ wq_w, const float* __restrict__ wk_w) {
    __shared__ int s_cnt, s_base;
    __shared__ int s_list[2048];
    int t = threadIdx.x;
    int lane = t & 31;
    if (t == 0) s_cnt = 0;
    __syncthreads();

    int base = (blockIdx.x * blockDim.x + t) * 8;
    bool valid = base < E;                    // E % 8 == 0
    int gs[8];
    int old[8];
    #pragma unroll
    for (int j = 0; j < 8; j++) { gs[j] = 0; old[j] = -1; }
    if (valid) {
        int4 a = *(const int4*)&seg[base];
        int4 b = *(const int4*)&seg[base + 4];
        gs[0]=a.x; gs[1]=a.y; gs[2]=a.z; gs[3]=a.w;
        gs[4]=b.x; gs[5]=b.y; gs[6]=b.z; gs[7]=b.w;
        #pragma unroll
        for (int j = 0; j < 8; j++) old[j] = atomicAdd(&g_counts[gs[j]], 1);
        #pragma unroll
        for (int j = 0; j < 8; j++)
            if (old[j] < CAP) g_geidx[(size_t)gs[j] * CAP + old[j]] = base + j;
        #pragma unroll
        for (int j = 0; j < 8; j++)
            if (old[j] == 1) s_list[atomicAdd(&s_cnt, 1)] = gs[j];
    }
    __syncthreads();
    if (t == 0) s_base = atomicAdd(&g_nslots, s_cnt);
    __syncthreads();
    for (int i = t; i < s_cnt; i += blockDim.x)
        g_slotg[s_base + i] = s_list[i];

    // ---- fc3 (redundant per block) + M rows (blocks 0..63) ----
    if (blockIdx.x < DD / 2) {
        __shared__ float red[4][8];
        __shared__ float mid[4];
        __shared__ float col[2][DD];
        int w = t >> 5;
        float hv = __ldg(&g_h2[t]);
        #pragma unroll
        for (int o = 0; o < 4; o++) {
            float p = hv * __ldg(&fc3_w[o*HH + t]);
            #pragma unroll
            for (int off = 16; off > 0; off >>= 1)
                p += __shfl_xor_sync(0xffffffffu, p, off);
            if (lane == 0) red[o][w] = p;
        }
        __syncthreads();
        if (t < 4) {
            float a = __ldg(&fc3_b[t]);
            #pragma unroll
            for (int ww = 0; ww < 8; ww++) a += red[t][ww];
            mid[t] = a;
        }
        __syncthreads();
        float m0 = mid[0], m1 = mid[1], m2 = mid[2], m3 = mid[3];

        int half = t >> 7;
        int c = t & (DD - 1);
        int r = blockIdx.x * 2 + half;
        const float2* wq2 = (const float2*)wq_w;
        const float2* wk2 = (const float2*)wk_w;
        float2 q = __ldg(&wq2[c*DD + r]);    // Wq[c, r]
        col[half][c] = m0 * q.x + m1 * q.y;
        __syncthreads();
        float acc = 0.f;
        #pragma unroll 16
        for (int o = 0; o < DD; o++) {
            float2 kv = __ldg(&wk2[o*DD + c]);
            acc += col[half][o] * (m2 * kv.x + m3 * kv.y);
        }
        g_M[r*DD + c] = acc;
    }
}

// ---------------- kernel 3: gather + GEMM + score + softmax ------------
// Phase B cols are now STRIDED float2 pairs c = 2*tx + 32*j: M loads become
// LDS.64 covering all 32 banks exactly once (conflict-free; was 4-way).
__global__ void __launch_bounds__(512, 2) k_u_score(
        const float* __restrict__ emb, const float* __restrict__ dists,
        const float* __restrict__ pref, float* __restrict__ out) {
    extern __shared__ float sh[];
    float* Msh  = sh;                          // DD*DD
    float* S    = sh + DD*DD;                  // 64 rows, stride SSTR
    int*  metaI = (int*)(S + 64*SSTR);         // 2 bufs x [sg|sc|e0..e3] x 64
    float* metaF = (float*)(metaI + 2*384);    // 2 bufs x [de0..de3] x 64
    __shared__ int curTile;
    int t = threadIdx.x;
    int lane = t & 31, w = t >> 5;             // w: 0..15
    for (int i = t; i < DD*DD/4; i += 512)
        ((float4*)Msh)[i] = ((const float4*)g_M)[i];
    float p0 = pref[0], p1 = pref[1];
    const float inv_scale = 0.011048543456039805f;  // 1/(8*sqrt(128))
    const float inv_sqrt2 = 0.7071067811865476f;
    int tx = t & 15, typ = t >> 4;
    int cb = tx * 2;                           // cols cb+32j, cb+32j+1 (j=0..3)
    int ns = g_nslots;
    int ntiles = (ns + 63) >> 6;

    // lanes 0..3 each fetch one slot's chain: slotg -> {counts, e-list int4,
    // dists for e0..e3} (stale e2/e3 indices are in-range => loads safe)
    auto prefetch = [&](int tile, int buf) {
        if (lane < 4) {
            int s0 = tile * 64;
            int nk = min(64, ns - s0);
            int k  = w * 4 + lane;
            int sg = (k < nk) ? __ldg(&g_slotg[s0 + k]) : -1;
            int sc = 0;
            int4 ev = make_int4(0, 0, 0, 0);
            float de0 = 0.f, de1 = 0.f, de2 = 0.f, de3 = 0.f;
            if (sg >= 0) {
                sc = __ldg(&g_counts[sg]);
                ev = __ldg((const int4*)&g_geidx[(size_t)sg * CAP]);  // e0..e3
                float2 a = __ldg((const float2*)&dists[2*ev.x]);
                float2 b = __ldg((const float2*)&dists[2*ev.y]);
                float2 c = __ldg((const float2*)&dists[2*ev.z]);
                float2 d = __ldg((const float2*)&dists[2*ev.w]);
                de0 = p0 * a.x + p1 * a.y;
                de1 = p0 * b.x + p1 * b.y;
                de2 = p0 * c.x + p1 * c.y;
                de3 = p0 * d.x + p1 * d.y;
            }
            int*   MI = metaI + buf * 384;
            float* MF = metaF + buf * 256;
            MI[k] = sg; MI[64 + k] = sc;
            MI[128 + k] = ev.x; MI[192 + k] = ev.y;
            MI[256 + k] = ev.z; MI[320 + k] = ev.w;
            MF[k] = de0; MF[64 + k] = de1; MF[128 + k] = de2; MF[192 + k] = de3;
        }
    };

    if (t == 0) curTile = atomicAdd(&g_tile, 1);
    __syncthreads();
    int ct = curTile;
    int buf = 0;
    if (ct < ntiles) prefetch(ct, 0);

    while (ct < ntiles) {
        if (t == 0) curTile = atomicAdd(&g_tile, 1);
        int*   MI = metaI + buf * 384;
        float* MF = metaF + buf * 256;

        // ---- Phase A: gather + sum (unconditional x0..x3, MLP = 16/lane) ----
        #pragma unroll
        for (int ss = 0; ss < 4; ss++) {
            int k  = w * 4 + ss;
            int sg = MI[k];
            float4 a = make_float4(0.f, 0.f, 0.f, 0.f);
            if (sg >= 0) {
                int cc = min(MI[64 + k], CAP);
                float4 x0 = __ldg(&((const float4*)(emb + (size_t)MI[128+k] * DD))[lane]);
                float4 x1 = __ldg(&((const float4*)(emb + (size_t)MI[192+k] * DD))[lane]);
                float4 x2 = __ldg(&((const float4*)(emb + (size_t)MI[256+k] * DD))[lane]);
                float4 x3 = __ldg(&((const float4*)(emb + (size_t)MI[320+k] * DD))[lane]);
                float m2 = (cc > 2) ? 1.f : 0.f;
                float m3 = (cc > 3) ? 1.f : 0.f;
                a.x = x0.x + x1.x + m2*x2.x + m3*x3.x;
                a.y = x0.y + x1.y + m2*x2.y + m3*x3.y;
                a.z = x0.z + x1.z + m2*x2.z + m3*x3.z;
                a.w = x0.w + x1.w + m2*x2.w + m3*x3.w;
                for (int j = 4; j < cc; j++) {
                    int e = __ldg(&g_geidx[(size_t)sg * CAP + j]);
                    float4 x = __ldg(&((const float4*)(emb + (size_t)e * DD))[lane]);
                    a.x += x.x; a.y += x.y; a.z += x.z; a.w += x.w;
                }
            }
            *(float4*)&S[k * SSTR + lane * 4] = a;
        }
        __syncthreads();                  // S ready; curTile visible

        int nt = curTile;
        if (nt < ntiles) prefetch(nt, buf ^ 1);   // hidden under GEMM

        // ---- Phase B: u[k][c] = sum_d S[k][d] * M[d][c], strided cols ----
        unsigned long long acc[2][4];
        #pragma unroll
        for (int i = 0; i < 2; i++)
            #pragma unroll
            for (int j = 0; j < 4; j++) acc[i][j] = 0ull;
        #pragma unroll 4
        for (int d = 0; d < DD; d++) {
            const float* mrow = &Msh[d*DD + cb];
            unsigned long long m0 = *(const unsigned long long*)&mrow[0];
            unsigned long long m1 = *(const unsigned long long*)&mrow[32];
            unsigned long long m2 = *(const unsigned long long*)&mrow[64];
            unsigned long long m3 = *(const unsigned long long*)&mrow[96];
            unsigned long long sa = pack2(S[(2*typ    ) * SSTR + d]);
            unsigned long long sb = pack2(S[(2*typ + 1) * SSTR + d]);
            fma2(acc[0][0], m0, sa); fma2(acc[0][1], m1, sa);
            fma2(acc[0][2], m2, sa); fma2(acc[0][3], m3, sa);
            fma2(acc[1][0], m0, sb); fma2(acc[1][1], m1, sb);
            fma2(acc[1][2], m2, sb); fma2(acc[1][3], m3, sb);
        }
        __syncthreads();
        #pragma unroll
        for (int i = 0; i < 2; i++) {
            float* row = &S[(2*typ + i) * SSTR + cb];
            *(unsigned long long*)&row[0]  = acc[i][0];
            *(unsigned long long*)&row[32] = acc[i][1];
            *(unsigned long long*)&row[64] = acc[i][2];
            *(unsigned long long*)&row[96] = acc[i][3];
        }
        __syncthreads();

        // ---- Phase C: per-slot softmax (meta + dists fully cached j<4) ----
        #pragma unroll
        for (int ss = 0; ss < 4; ss++) {
            int k  = w * 4 + ss;
            int sg = MI[k];
            if (sg < 0) continue;
            int sc = MI[64 + k];
            float fc = (float)sc;
            int cc = min(sc, CAP);
            float4 u4 = *(float4*)&S[k * SSTR + lane * 4];
            float denom = 0.f, myex = 0.f;
            int mye = 0;
            for (int j = 0; j < cc; j++) {
                int e; float de;
                if (j < 4) { e = MI[128 + 64*j + k]; de = MF[64*j + k]; }
                else {
                    e = __ldg(&g_geidx[(size_t)sg * CAP + j]);
                    float2 dd = __ldg((const float2*)&dists[2*e]);
                    de = p0 * dd.x + p1 * dd.y;
                }
                float4 x = __ldg(&((const float4*)(emb + (size_t)e * DD))[lane]);
                float dot = u4.x*x.x + u4.y*x.y + u4.z*x.z + u4.w*x.w;
                #pragma unroll
                for (int o = 16; o > 0; o >>= 1)
                    dot += __shfl_xor_sync(0xffffffffu, dot, o);
                float s = dot * inv_scale / fc - de * inv_sqrt2;
                float ex = expf(10.0f * tanhf(s));   // clipped: exp is fp32-safe
                denom += ex;
                if (lane == j) { mye = e; myex = ex; }
            }
            if (lane < cc) out[mye] = myex / denom;
        }
        __syncthreads();
        buf ^= 1;
        ct = nt;
    }
}

// ---------------- launch ----------------
extern "C" void kernel_launch(void* const* d_in, const int* in_sizes, int n_in,
                              void* d_out, int out_size) {
    const float* pref     = (const float*)d_in[0];
    const float* dists    = (const float*)d_in[1];
    const float* edge_emb = (const float*)d_in[2];
    const int*   seg      = (const int*)  d_in[3];
    const float* fc1_w    = (const float*)d_in[4];
    const float* fc1_b    = (const float*)d_in[5];
    const float* fc2_w    = (const float*)d_in[6];
    const float* fc2_b    = (const float*)d_in[7];
    const float* fc3_w    = (const float*)d_in[8];
    const float* fc3_b    = (const float*)d_in[9];
    const float* wq_w     = (const float*)d_in[10];
    const float* wk_w     = (const float*)d_in[11];
    float* out = (float*)d_out;

    int E   = in_sizes[3];
    int EB4 = (E/4 + 255) / 256;
    int EB8 = (E/8 + 255) / 256;

    const int KU_SMEM = (DD*DD + 64*SSTR) * (int)sizeof(float)
                      + 2*384*(int)sizeof(int) + 2*256*(int)sizeof(float);
    cudaFuncSetAttribute(k_u_score, cudaFuncAttributeMaxDynamicSharedMemorySize, KU_SMEM);

    k_nop        <<<1, 32>>>();          // keeps ncu capture on k_u_score
    k_zero_hyper <<<EB4, 256>>>(E, out, pref, fc1_w, fc1_b, fc2_w, fc2_b);
    k_count_m    <<<EB8, 256>>>(seg, E, fc3_w, fc3_b, wq_w, wk_w);
    k_u_score    <<<296, 512, KU_SMEM>>>(edge_emb, dists, pref, out);
}

// round 17
// speedup vs baseline: 1.4049x; 1.0440x over previous
#include <cuda_runtime.h>
#include <math.h>

#define DD   128        // embedding dim
#define HH   256        // hyper hidden
#define EMAX 500000
#define SLOTMAX 250000
#define CAP  8          // max edges tracked per group (P(c>8) ~ 1e-12/pair)
#define SSTR (DD + 4)   // padded S row stride

// ---------------- device scratch (static; no allocation) ----------------
__device__ float g_h2 [HH];                    // hypernet hidden layer 2
__device__ float g_M [DD*DD];
__device__ int   g_counts[EMAX];
__device__ int   g_slotg [SLOTMAX];            // slot -> group id
__device__ int   g_geidx [(size_t)EMAX * CAP]; // per-group edge lists (32B rows)
__device__ int   g_nslots;
__device__ int   g_tile;                       // dynamic tile counter

// ---------------- helpers ----------------
__device__ __forceinline__ unsigned long long pack2(float s) {
    unsigned long long r;
    asm("mov.b64 %0, {%1, %1};" : "=l"(r) : "r"(__float_as_uint(s)));
    return r;
}
__device__ __forceinline__ void fma2(unsigned long long& d,
                                     unsigned long long a, unsigned long long b) {
    asm("fma.rn.f32x2 %0, %1, %2, %0;" : "+l"(d) : "l"(a), "l"(b));
}

// no-op FIRST: keeps ncu's capture slot (launch #4) on k_u_score
__global__ void k_nop() {}

// ---------------- kernel 1: zero + out=1 + DISTRIBUTED fc1/fc2 ----------
__global__ void k_zero_hyper(int E, float* __restrict__ out,
                             const float* __restrict__ pref,
                             const float* __restrict__ fc1_w, const float* __restrict__ fc1_b,
                             const float* __restrict__ fc2_w, const float* __restrict__ fc2_b) {
    int i = blockIdx.x * blockDim.x + threadIdx.x;   // quad index (E % 4 == 0)
    if (i * 4 < E) {
        ((int4*)g_counts)[i] = make_int4(0, 0, 0, 0);
        ((float4*)out)[i]    = make_float4(1.f, 1.f, 1.f, 1.f);  // singleton answer
    }
    if (i == 0) { g_nslots = 0; g_tile = 0; }

    int b = blockIdx.x;
    if (b < HH) {                     // block b computes h2[b]
        __shared__ float red[8];
        int t = threadIdx.x;
        int lane = t & 31, w = t >> 5;
        float p0 = pref[0], p1 = pref[1];
        float h1t = p0 * __ldg(&fc1_w[2*t]) + p1 * __ldg(&fc1_w[2*t + 1])
                  + __ldg(&fc1_b[t]);
        float p = h1t * __ldg(&fc2_w[b*HH + t]);
        #pragma unroll
        for (int off = 16; off > 0; off >>= 1)
            p += __shfl_xor_sync(0xffffffffu, p, off);
        if (lane == 0) red[w] = p;
        __syncthreads();
        if (t == 0) {
            float a = __ldg(&fc2_b[b]);
            #pragma unroll
            for (int ww = 0; ww < 8; ww++) a += red[ww];
            g_h2[b] = a;
        }
    }
}

// ---------------- kernel 2: count + lists + BLOCK-AGGREGATED slot claim --
__global__ void k_count_m(const int* __restrict__ seg, int E,
                          const float* __restrict__ fc3_w, const float* __restrict__ fc3_b,
                          const float* __restrict__ wq_w, const float* __restrict__ wk_w) {
    __shared__ int s_cnt, s_base;
    __shared__ int s_list[2048];
    int t = threadIdx.x;
    int lane = t & 31;
    if (t == 0) s_cnt = 0;
    __syncthreads();

    int base = (blockIdx.x * blockDim.x + t) * 8;
    bool valid = base < E;                    // E % 8 == 0
    int gs[8];
    int old[8];
    #pragma unroll
    for (int j = 0; j < 8; j++) { gs[j] = 0; old[j] = -1; }
    if (valid) {
        int4 a = *(const int4*)&seg[base];
        int4 b = *(const int4*)&seg[base + 4];
        gs[0]=a.x; gs[1]=a.y; gs[2]=a.z; gs[3]=a.w;
        gs[4]=b.x; gs[5]=b.y; gs[6]=b.z; gs[7]=b.w;
        #pragma unroll
        for (int j = 0; j < 8; j++) old[j] = atomicAdd(&g_counts[gs[j]], 1);
        #pragma unroll
        for (int j = 0; j < 8; j++)
            if (old[j] < CAP) g_geidx[(size_t)gs[j] * CAP + old[j]] = base + j;
        #pragma unroll
        for (int j = 0; j < 8; j++)
            if (old[j] == 1) s_list[atomicAdd(&s_cnt, 1)] = gs[j];
    }
    __syncthreads();
    if (t == 0) s_base = atomicAdd(&g_nslots, s_cnt);
    __syncthreads();
    for (int i = t; i < s_cnt; i += blockDim.x)
        g_slotg[s_base + i] = s_list[i];

    // ---- fc3 (redundant per block) + M rows (blocks 0..63) ----
    if (blockIdx.x < DD / 2) {
        __shared__ float red[4][8];
        __shared__ float mid[4];
        __shared__ float col[2][DD];
        int w = t >> 5;
        float hv = __ldg(&g_h2[t]);
        #pragma unroll
        for (int o = 0; o < 4; o++) {
            float p = hv * __ldg(&fc3_w[o*HH + t]);
            #pragma unroll
            for (int off = 16; off > 0; off >>= 1)
                p += __shfl_xor_sync(0xffffffffu, p, off);
            if (lane == 0) red[o][w] = p;
        }
        __syncthreads();
        if (t < 4) {
            float a = __ldg(&fc3_b[t]);
            #pragma unroll
            for (int ww = 0; ww < 8; ww++) a += red[t][ww];
            mid[t] = a;
        }
        __syncthreads();
        float m0 = mid[0], m1 = mid[1], m2 = mid[2], m3 = mid[3];

        int half = t >> 7;
        int c = t & (DD - 1);
        int r = blockIdx.x * 2 + half;
        const float2* wq2 = (const float2*)wq_w;
        const float2* wk2 = (const float2*)wk_w;
        float2 q = __ldg(&wq2[c*DD + r]);    // Wq[c, r]
        col[half][c] = m0 * q.x + m1 * q.y;
        __syncthreads();
        float acc = 0.f;
        #pragma unroll 16
        for (int o = 0; o < DD; o++) {
            float2 kv = __ldg(&wk2[o*DD + c]);
            acc += col[half][o] * (m2 * kv.x + m3 * kv.y);
        }
        g_M[r*DD + c] = acc;
    }
}

// ---------------- kernel 3: gather + GEMM + score + softmax ------------
// Phase B: cols 4tx..4tx+3 and 4tx+64..+67 per thread -> M via 2x LDS.128
// (conflict-free, 2 wf each), S via LDS.64 with d-unroll 2. 26 issue slots /
// 10 wavefronts per 2d (was 32/12).
__global__ void __launch_bounds__(512, 2) k_u_score(
        const float* __restrict__ emb, const float* __restrict__ dists,
        const float* __restrict__ pref, float* __restrict__ out) {
    extern __shared__ float sh[];
    float* Msh  = sh;                          // DD*DD
    float* S    = sh + DD*DD;                  // 64 rows, stride SSTR
    int*  metaI = (int*)(S + 64*SSTR);         // 2 bufs x [sg|sc|e0..e3] x 64
    float* metaF = (float*)(metaI + 2*384);    // 2 bufs x [de0..de3] x 64
    __shared__ int curTile;
    int t = threadIdx.x;
    int lane = t & 31, w = t >> 5;             // w: 0..15
    for (int i = t; i < DD*DD/4; i += 512)
        ((float4*)Msh)[i] = ((const float4*)g_M)[i];
    float p0 = pref[0], p1 = pref[1];
    const float inv_scale = 0.011048543456039805f;  // 1/(8*sqrt(128))
    const float inv_sqrt2 = 0.7071067811865476f;
    int tx = t & 15, typ = t >> 4;
    int cb = tx * 4;                           // cols cb..cb+3, cb+64..cb+67
    int ns = g_nslots;
    int ntiles = (ns + 63) >> 6;

    // lanes 0..3 each fetch one slot's chain: slotg -> {counts, e-list int4,
    // dists for e0..e3} (stale e2/e3 indices are in-range => loads safe)
    auto prefetch = [&](int tile, int buf) {
        if (lane < 4) {
            int s0 = tile * 64;
            int nk = min(64, ns - s0);
            int k  = w * 4 + lane;
            int sg = (k < nk) ? __ldg(&g_slotg[s0 + k]) : -1;
            int sc = 0;
            int4 ev = make_int4(0, 0, 0, 0);
            float de0 = 0.f, de1 = 0.f, de2 = 0.f, de3 = 0.f;
            if (sg >= 0) {
                sc = __ldg(&g_counts[sg]);
                ev = __ldg((const int4*)&g_geidx[(size_t)sg * CAP]);  // e0..e3
                float2 a = __ldg((const float2*)&dists[2*ev.x]);
                float2 b = __ldg((const float2*)&dists[2*ev.y]);
                float2 c = __ldg((const float2*)&dists[2*ev.z]);
                float2 d = __ldg((const float2*)&dists[2*ev.w]);
                de0 = p0 * a.x + p1 * a.y;
                de1 = p0 * b.x + p1 * b.y;
                de2 = p0 * c.x + p1 * c.y;
                de3 = p0 * d.x + p1 * d.y;
            }
            int*   MI = metaI + buf * 384;
            float* MF = metaF + buf * 256;
            MI[k] = sg; MI[64 + k] = sc;
            MI[128 + k] = ev.x; MI[192 + k] = ev.y;
            MI[256 + k] = ev.z; MI[320 + k] = ev.w;
            MF[k] = de0; MF[64 + k] = de1; MF[128 + k] = de2; MF[192 + k] = de3;
        }
    };

    if (t == 0) curTile = atomicAdd(&g_tile, 1);
    __syncthreads();
    int ct = curTile;
    int buf = 0;
    if (ct < ntiles) prefetch(ct, 0);

    while (ct < ntiles) {
        if (t == 0) curTile = atomicAdd(&g_tile, 1);
        int*   MI = metaI + buf * 384;
        float* MF = metaF + buf * 256;

        // ---- Phase A: gather + sum (unconditional x0..x3, MLP = 16/lane) ----
        #pragma unroll
        for (int ss = 0; ss < 4; ss++) {
            int k  = w * 4 + ss;
            int sg = MI[k];
            float4 a = make_float4(0.f, 0.f, 0.f, 0.f);
            if (sg >= 0) {
                int cc = min(MI[64 + k], CAP);
                float4 x0 = __ldg(&((const float4*)(emb + (size_t)MI[128+k] * DD))[lane]);
                float4 x1 = __ldg(&((const float4*)(emb + (size_t)MI[192+k] * DD))[lane]);
                float4 x2 = __ldg(&((const float4*)(emb + (size_t)MI[256+k] * DD))[lane]);
                float4 x3 = __ldg(&((const float4*)(emb + (size_t)MI[320+k] * DD))[lane]);
                float m2 = (cc > 2) ? 1.f : 0.f;
                float m3 = (cc > 3) ? 1.f : 0.f;
                a.x = x0.x + x1.x + m2*x2.x + m3*x3.x;
                a.y = x0.y + x1.y + m2*x2.y + m3*x3.y;
                a.z = x0.z + x1.z + m2*x2.z + m3*x3.z;
                a.w = x0.w + x1.w + m2*x2.w + m3*x3.w;
                for (int j = 4; j < cc; j++) {
                    int e = __ldg(&g_geidx[(size_t)sg * CAP + j]);
                    float4 x = __ldg(&((const float4*)(emb + (size_t)e * DD))[lane]);
                    a.x += x.x; a.y += x.y; a.z += x.z; a.w += x.w;
                }
            }
            *(float4*)&S[k * SSTR + lane * 4] = a;
        }
        __syncthreads();                  // S ready; curTile visible

        int nt = curTile;
        if (nt < ntiles) prefetch(nt, buf ^ 1);   // hidden under GEMM

        // ---- Phase B: u[k][c] = sum_d S[k][d] * M[d][c] ----
        unsigned long long acc[2][4];
        #pragma unroll
        for (int i = 0; i < 2; i++)
            #pragma unroll
            for (int j = 0; j < 4; j++) acc[i][j] = 0ull;
        #pragma unroll 2
        for (int d = 0; d < DD; d += 2) {
            double2 ma0 = *(const double2*)&Msh[(d  )*DD + cb];       // cols cb..+3
            double2 mb0 = *(const double2*)&Msh[(d  )*DD + cb + 64];  // cols cb+64..+67
            double2 ma1 = *(const double2*)&Msh[(d+1)*DD + cb];
            double2 mb1 = *(const double2*)&Msh[(d+1)*DD + cb + 64];
            float2 s2a = *(const float2*)&S[(2*typ    ) * SSTR + d];  // S[d], S[d+1]
            float2 s2b = *(const float2*)&S[(2*typ + 1) * SSTR + d];
            unsigned long long sa0 = pack2(s2a.x), sa1 = pack2(s2a.y);
            unsigned long long sb0 = pack2(s2b.x), sb1 = pack2(s2b.y);
            fma2(acc[0][0], __double_as_longlong(ma0.x), sa0);
            fma2(acc[0][1], __double_as_longlong(ma0.y), sa0);
            fma2(acc[0][2], __double_as_longlong(mb0.x), sa0);
            fma2(acc[0][3], __double_as_longlong(mb0.y), sa0);
            fma2(acc[1][0], __double_as_longlong(ma0.x), sb0);
            fma2(acc[1][1], __double_as_longlong(ma0.y), sb0);
            fma2(acc[1][2], __double_as_longlong(mb0.x), sb0);
            fma2(acc[1][3], __double_as_longlong(mb0.y), sb0);
            fma2(acc[0][0], __double_as_longlong(ma1.x), sa1);
            fma2(acc[0][1], __double_as_longlong(ma1.y), sa1);
            fma2(acc[0][2], __double_as_longlong(mb1.x), sa1);
            fma2(acc[0][3], __double_as_longlong(mb1.y), sa1);
            fma2(acc[1][0], __double_as_longlong(ma1.x), sb1);
            fma2(acc[1][1], __double_as_longlong(ma1.y), sb1);
            fma2(acc[1][2], __double_as_longlong(mb1.x), sb1);
            fma2(acc[1][3], __double_as_longlong(mb1.y), sb1);
        }
        __syncthreads();
        #pragma unroll
        for (int i = 0; i < 2; i++) {
            float* row = &S[(2*typ + i) * SSTR + cb];   // 16B-aligned
            *(double2*)&row[0]  = make_double2(__longlong_as_double(acc[i][0]),
                                               __longlong_as_double(acc[i][1]));
            *(double2*)&row[64] = make_double2(__longlong_as_double(acc[i][2]),
                                               __longlong_as_double(acc[i][3]));
        }
        __syncthreads();

        // ---- Phase C: per-slot softmax (meta + dists fully cached j<4) ----
        #pragma unroll
        for (int ss = 0; ss < 4; ss++) {
            int k  = w * 4 + ss;
            int sg = MI[k];
            if (sg < 0) continue;
            int sc = MI[64 + k];
            float fc = (float)sc;
            int cc = min(sc, CAP);
            float4 u4 = *(float4*)&S[k * SSTR + lane * 4];
            float denom = 0.f, myex = 0.f;
            int mye = 0;
            for (int j = 0; j < cc; j++) {
                int e; float de;
                if (j < 4) { e = MI[128 + 64*j + k]; de = MF[64*j + k]; }
                else {
                    e = __ldg(&g_geidx[(size_t)sg * CAP + j]);
                    float2 dd = __ldg((const float2*)&dists[2*e]);
                    de = p0 * dd.x + p1 * dd.y;
                }
                float4 x = __ldg(&((const float4*)(emb + (size_t)e * DD))[lane]);
                float dot = u4.x*x.x + u4.y*x.y + u4.z*x.z + u4.w*x.w;
                #pragma unroll
                for (int o = 16; o > 0; o >>= 1)
                    dot += __shfl_xor_sync(0xffffffffu, dot, o);
                float s = dot * inv_scale / fc - de * inv_sqrt2;
                float ex = expf(10.0f * tanhf(s));   // clipped: exp is fp32-safe
                denom += ex;
                if (lane == j) { mye = e; myex = ex; }
            }
            if (lane < cc) out[mye] = myex / denom;
        }
        __syncthreads();
        buf ^= 1;
        ct = nt;
    }
}

// ---------------- launch ----------------
extern "C" void kernel_launch(void* const* d_in, const int* in_sizes, int n_in,
                              void* d_out, int out_size) {
    const float* pref     = (const float*)d_in[0];
    const float* dists    = (const float*)d_in[1];
    const float* edge_emb = (const float*)d_in[2];
    const int*   seg      = (const int*)  d_in[3];
    const float* fc1_w    = (const float*)d_in[4];
    const float* fc1_b    = (const float*)d_in[5];
    const float* fc2_w    = (const float*)d_in[6];
    const float* fc2_b    = (const float*)d_in[7];
    const float* fc3_w    = (const float*)d_in[8];
    const float* fc3_b    = (const float*)d_in[9];
    const float* wq_w     = (const float*)d_in[10];
    const float* wk_w     = (const float*)d_in[11];
    float* out = (float*)d_out;

    int E   = in_sizes[3];
    int EB4 = (E/4 + 255) / 256;
    int EB8 = (E/8 + 255) / 256;

    const int KU_SMEM = (DD*DD + 64*SSTR) * (int)sizeof(float)
                      + 2*384*(int)sizeof(int) + 2*256*(int)sizeof(float);
    cudaFuncSetAttribute(k_u_score, cudaFuncAttributeMaxDynamicSharedMemorySize, KU_SMEM);

    k_nop        <<<1, 32>>>();          // keeps ncu capture on k_u_score
    k_zero_hyper <<<EB4, 256>>>(E, out, pref, fc1_w, fc1_b, fc2_w, fc2_b);
    k_count_m    <<<EB8, 256>>>(seg, E, fc3_w, fc3_b, wq_w, wk_w);
    k_u_score    <<<296, 512, KU_SMEM>>>(edge_emb, dists, pref, out);
}